// round 1
// baseline (speedup 1.0000x reference)
#include <cuda_runtime.h>

// Problem constants
#define Bn 131072
#define Cn 128
#define En 128
#define TS 64          // samples per block (main kernel)
#define PTS 66         // padded row stride (floats) for transposed predict tile

// ArcFace constants (m = 1.0, s = 100)
#define COSM 0.5403023058681398f
#define SINM 0.8414709848078965f
#define THv  (-0.5403023058681398f)
#define MMv  0.8414709848078965f
#define Sv   100.0f

// Scratch (no allocation allowed -> device globals)
__device__ float g_wnt[En * Cn];     // normalized weight, transposed: [k][c]
__device__ int   g_labels[Bn];
__device__ float g_bsum[Bn / TS];    // per-block NLL sums (2048)

typedef unsigned long long u64;

__device__ __forceinline__ u64 pack2(float a, float b) {
    u64 r; asm("mov.b64 %0,{%1,%2};" : "=l"(r) : "f"(a), "f"(b)); return r;
}
__device__ __forceinline__ void unpack2(u64 v, float& a, float& b) {
    asm("mov.b64 {%0,%1},%2;" : "=f"(a), "=f"(b) : "l"(v));
}
// d = a * b + d  (two independent fp32 FMAs per instruction)
__device__ __forceinline__ void fma2(u64& d, u64 a, u64 b) {
    asm("fma.rn.f32x2 %0,%1,%2,%0;" : "+l"(d) : "l"(a), "l"(b));
}

// ---------------------------------------------------------------------------
// prep: normalize weight rows (transposed output) + extract labels from one-hot
// grid: Bn/8 blocks x 256 threads, one warp per target row
// ---------------------------------------------------------------------------
__global__ void prep_kernel(const float* __restrict__ target,
                            const float* __restrict__ weight)
{
    const int lane = threadIdx.x & 31;
    const int w    = threadIdx.x >> 5;

    // Weight normalization: first 16 blocks, one warp per weight row.
    if (blockIdx.x < (Cn / 8)) {
        const int row = blockIdx.x * 8 + w;
        float v0 = weight[row * En + lane];
        float v1 = weight[row * En + lane + 32];
        float v2 = weight[row * En + lane + 64];
        float v3 = weight[row * En + lane + 96];
        float ss = v0 * v0 + v1 * v1 + v2 * v2 + v3 * v3;
        #pragma unroll
        for (int o = 16; o; o >>= 1) ss += __shfl_xor_sync(0xffffffffu, ss, o);
        float r = 1.0f / fmaxf(sqrtf(ss), 1e-12f);
        g_wnt[(lane)      * Cn + row] = v0 * r;
        g_wnt[(lane + 32) * Cn + row] = v1 * r;
        g_wnt[(lane + 64) * Cn + row] = v2 * r;
        g_wnt[(lane + 96) * Cn + row] = v3 * r;
    }

    // Labels: one warp per sample (argmax of one-hot row).
    const int sample = blockIdx.x * 8 + w;
    const float4 t = reinterpret_cast<const float4*>(target)[sample * (Cn / 4) + lane];
    int idx = -1;
    if (t.x > 0.5f) idx = lane * 4 + 0;
    if (t.y > 0.5f) idx = lane * 4 + 1;
    if (t.z > 0.5f) idx = lane * 4 + 2;
    if (t.w > 0.5f) idx = lane * 4 + 3;
    #pragma unroll
    for (int o = 16; o; o >>= 1) idx = max(idx, __shfl_xor_sync(0xffffffffu, idx, o));
    if (lane == 0) g_labels[sample] = idx;
}

// ---------------------------------------------------------------------------
// main: fused normalize(predict) @ wn.T -> arcface logits -> per-sample NLL
// grid: Bn/TS blocks x 256 threads. ~97 KB dynamic smem, 2 blocks/SM.
// Each warp owns 8 samples; f32x2 accumulators paired over samples.
// ---------------------------------------------------------------------------
__global__ void __launch_bounds__(256, 2)
arc_main(const float* __restrict__ predict)
{
    extern __shared__ float sm[];
    float* ws   = sm;                         // [128][128]   wn_t      (64 KB)
    float* pt   = sm + En * Cn;               // [128][PTS]   predict^T (33 KB)
    int*   slab = (int*)(pt + En * PTS);      // [64] labels
    float* wsum = (float*)(slab + TS);        // [8] warp partials

    const int tid   = threadIdx.x;
    const int lane  = tid & 31;
    const int w     = tid >> 5;
    const int blk   = blockIdx.x;
    const int sbase = w * 8;                  // this warp's first local sample

    // Stage wn_t: 16384 floats via float4
    {
        const float4* g  = (const float4*)g_wnt;
        float4*       s4 = (float4*)ws;
        #pragma unroll
        for (int i = 0; i < 16; i++) s4[i * 256 + tid] = g[i * 256 + tid];
    }
    if (tid < TS) slab[tid] = g_labels[blk * TS + tid];

    // Load + normalize + transpose this warp's 8 predict rows into pt[k][s].
    // Per-lane k = {lane, lane+32, lane+64, lane+96} -> bank-friendly STS.
    #pragma unroll
    for (int s8 = 0; s8 < 8; s8++) {
        const int sl = sbase + s8;
        const float* prow = predict + (size_t)(blk * TS + sl) * En;
        float v0 = prow[lane];
        float v1 = prow[lane + 32];
        float v2 = prow[lane + 64];
        float v3 = prow[lane + 96];
        float ss = v0 * v0 + v1 * v1 + v2 * v2 + v3 * v3;
        #pragma unroll
        for (int o = 16; o; o >>= 1) ss += __shfl_xor_sync(0xffffffffu, ss, o);
        float r = 1.0f / fmaxf(sqrtf(ss), 1e-12f);
        pt[(lane)      * PTS + sl] = v0 * r;
        pt[(lane + 32) * PTS + sl] = v1 * r;
        pt[(lane + 64) * PTS + sl] = v2 * r;
        pt[(lane + 96) * PTS + sl] = v3 * r;
    }
    __syncthreads();

    // acc[c][sp]: cols {lane+32c}, sample pair {2sp, 2sp+1} (lo, hi)
    u64 acc[4][4];
    #pragma unroll
    for (int c = 0; c < 4; c++)
        #pragma unroll
        for (int sp = 0; sp < 4; sp++) acc[c][sp] = 0ull;

    #pragma unroll 4
    for (int k = 0; k < En; k++) {
        u64 wd[4];
        #pragma unroll
        for (int c = 0; c < 4; c++) {
            float wv = ws[k * Cn + lane + 32 * c];
            wd[c] = pack2(wv, wv);
        }
        const u64* pp = (const u64*)(pt + k * PTS + sbase);  // 8B-aligned (PTS even)
        #pragma unroll
        for (int sp = 0; sp < 4; sp++) {
            u64 p2 = pp[sp];                                  // broadcast LDS.64
            #pragma unroll
            for (int c = 0; c < 4; c++) fma2(acc[c][sp], p2, wd[c]);
        }
    }

    // Epilogue: per sample -> arcface margin + log-softmax NLL
    float nll_acc = 0.0f;
    #pragma unroll
    for (int s = 0; s < 8; s++) {
        const int sp = s >> 1, h = s & 1;
        float lo, hi, c0, c1, c2, c3;
        unpack2(acc[0][sp], lo, hi); c0 = h ? hi : lo;
        unpack2(acc[1][sp], lo, hi); c1 = h ? hi : lo;
        unpack2(acc[2][sp], lo, hi); c2 = h ? hi : lo;
        unpack2(acc[3][sp], lo, hi); c3 = h ? hi : lo;

        const int lbl = slab[sbase + s];
        const int lc  = lbl >> 5;      // which col-slot
        const int ll  = lbl & 31;      // which lane

        float csel = (lc == 0) ? c0 : ((lc == 1) ? c1 : ((lc == 2) ? c2 : c3));
        float cs = __shfl_sync(0xffffffffu, csel, ll);   // label cosine, all lanes
        float sn  = sqrtf(fmaxf(1.0f - cs * cs, 0.0f));
        float phi = (cs > THv) ? (cs * COSM - sn * SINM) : (cs - MMv);
        float zl  = Sv * phi;

        float z0 = (lane == ll && lc == 0) ? zl : Sv * c0;
        float z1 = (lane == ll && lc == 1) ? zl : Sv * c1;
        float z2 = (lane == ll && lc == 2) ? zl : Sv * c2;
        float z3 = (lane == ll && lc == 3) ? zl : Sv * c3;

        float m = fmaxf(fmaxf(z0, z1), fmaxf(z2, z3));
        #pragma unroll
        for (int o = 16; o; o >>= 1) m = fmaxf(m, __shfl_xor_sync(0xffffffffu, m, o));

        float se = __expf(z0 - m) + __expf(z1 - m) + __expf(z2 - m) + __expf(z3 - m);
        #pragma unroll
        for (int o = 16; o; o >>= 1) se += __shfl_xor_sync(0xffffffffu, se, o);

        nll_acc += (m + __logf(se)) - zl;
    }

    if (lane == 0) wsum[w] = nll_acc;
    __syncthreads();
    if (tid == 0) {
        float t = 0.0f;
        #pragma unroll
        for (int i = 0; i < 8; i++) t += wsum[i];
        g_bsum[blk] = t;
    }
}

// ---------------------------------------------------------------------------
// finish: deterministic reduction of block partials -> mean
// ---------------------------------------------------------------------------
__global__ void finish_kernel(float* __restrict__ out)
{
    __shared__ double sh[256];
    double t = 0.0;
    for (int i = threadIdx.x; i < Bn / TS; i += 256) t += (double)g_bsum[i];
    sh[threadIdx.x] = t;
    __syncthreads();
    #pragma unroll
    for (int s = 128; s; s >>= 1) {
        if (threadIdx.x < s) sh[threadIdx.x] += sh[threadIdx.x + s];
        __syncthreads();
    }
    if (threadIdx.x == 0) out[0] = (float)(sh[0] / (double)Bn);
}

// ---------------------------------------------------------------------------
extern "C" void kernel_launch(void* const* d_in, const int* in_sizes, int n_in,
                              void* d_out, int out_size)
{
    (void)in_sizes; (void)n_in; (void)out_size;
    const float* predict = (const float*)d_in[0];
    const float* target  = (const float*)d_in[1];
    const float* weight  = (const float*)d_in[2];

    const int smem_bytes = (En * Cn + En * PTS) * 4 + TS * 4 + 8 * 4;  // ~97.3 KB
    cudaFuncSetAttribute(arc_main, cudaFuncAttributeMaxDynamicSharedMemorySize,
                         smem_bytes);

    prep_kernel<<<Bn / 8, 256>>>(target, weight);
    arc_main<<<Bn / TS, 256, smem_bytes>>>(predict);
    finish_kernel<<<1, 256>>>((float*)d_out);
}

// round 4
// speedup vs baseline: 1.8125x; 1.8125x over previous
#include <cuda_runtime.h>
#include <cuda_fp16.h>
#include <cstdint>

// Problem constants
#define Bn 131072
#define Cn 128
#define En 128
#define TM 128              // samples per block
#define NBLK (Bn / TM)      // 1024 blocks
#define PADH 136            // smem row stride in halves (272 bytes) -> conflict-free

// ArcFace constants (m = 1.0, s = 100)
#define COSM 0.5403023058681398f
#define SINM 0.8414709848078965f
#define THv  (-0.5403023058681398f)
#define MMv  0.8414709848078965f
#define Sv   100.0f

// Scratch (no allocation allowed -> device globals)
__device__ __half g_wn16[Cn * En];   // normalized weight fp16, row-major [C][E]
__device__ float  g_bsum[NBLK];
__device__ int    g_cnt;             // zero-init; reset by last block each launch

// smem byte offsets
#define OFF_A    0                   // half[128][136] = 34816 B
#define OFF_B    34816               // half[128][136] = 34816 B
#define OFF_SLAB 69632               // int[128]
#define OFF_RED  70144               // float[256]
#define OFF_FLAG 71168               // int
#define SMEM_SZ  71200

__device__ __forceinline__ void hmma16816(float& c0, float& c1, float& c2, float& c3,
                                          uint32_t a0, uint32_t a1, uint32_t a2, uint32_t a3,
                                          uint32_t b0, uint32_t b1) {
    asm volatile(
        "mma.sync.aligned.m16n8k16.row.col.f32.f16.f16.f32 "
        "{%0,%1,%2,%3}, {%4,%5,%6,%7}, {%8,%9}, {%0,%1,%2,%3};"
        : "+f"(c0), "+f"(c1), "+f"(c2), "+f"(c3)
        : "r"(a0), "r"(a1), "r"(a2), "r"(a3), "r"(b0), "r"(b1));
}

// ---------------------------------------------------------------------------
// prep: normalize weight rows -> fp16 row-major global. 16 blocks x 256 thr.
// ---------------------------------------------------------------------------
__global__ void prep_kernel(const float* __restrict__ weight)
{
    const int lane = threadIdx.x & 31;
    const int w    = threadIdx.x >> 5;
    const int row  = blockIdx.x * 8 + w;

    float4 v = reinterpret_cast<const float4*>(weight)[row * 32 + lane];
    float ss = v.x * v.x + v.y * v.y + v.z * v.z + v.w * v.w;
    #pragma unroll
    for (int o = 16; o; o >>= 1) ss += __shfl_xor_sync(0xffffffffu, ss, o);
    float r = 1.0f / fmaxf(sqrtf(ss), 1e-12f);

    __half2 h0 = __floats2half2_rn(v.x * r, v.y * r);
    __half2 h1 = __floats2half2_rn(v.z * r, v.w * r);
    unsigned long long pk;
    asm("mov.b64 %0,{%1,%2};" : "=l"(pk)
        : "r"(*(uint32_t*)&h0), "r"(*(uint32_t*)&h1));
    *reinterpret_cast<unsigned long long*>(
        reinterpret_cast<char*>(g_wn16) + row * 256 + lane * 8) = pk;
}

// NLL from label-EXCLUDED (m, se) and label cosine cs. Strictly additive.
__device__ __forceinline__ float row_nll(float m, float se, float cs) {
    float sn  = sqrtf(fmaxf(1.0f - cs * cs, 0.0f));
    float phi = (cs > THv) ? (cs * COSM - sn * SINM) : (cs - MMv);
    float zl  = Sv * phi;
    float mp  = fmaxf(m, zl);
    float se2 = se * __expf(m - mp) + __expf(zl - mp);
    return (mp + __logf(se2)) - zl;
}

// ---------------------------------------------------------------------------
// main: per 128-sample tile — normalize predict->fp16 A, labels, HMMA GEMM,
// fused arcface + additive online log-softmax; last block reduces mean.
// ---------------------------------------------------------------------------
__global__ void __launch_bounds__(256, 2)
arc_main(const float* __restrict__ predict,
         const float* __restrict__ target,
         float* __restrict__ out)
{
    extern __shared__ char sm[];
    char*  sA   = sm + OFF_A;
    char*  sB   = sm + OFF_B;
    int*   slab = (int*)(sm + OFF_SLAB);
    float* red  = (float*)(sm + OFF_RED);
    int*   flag = (int*)(sm + OFF_FLAG);

    const int tid  = threadIdx.x;
    const int lane = tid & 31;
    const int w    = tid >> 5;
    const int blk  = blockIdx.x;

    // ---- B tile: copy normalized fp16 weights into padded smem ----
    {
        const uint32_t* gw = (const uint32_t*)g_wn16;   // 8192 u32
        #pragma unroll
        for (int i = 0; i < 32; i++) {
            int idx = i * 256 + tid;
            *(uint32_t*)(sB + (idx >> 6) * (PADH * 2) + (idx & 63) * 4) = gw[idx];
        }
    }

    // ---- A tile: load + normalize + fp16 + padded store (warp per row) ----
    #pragma unroll 2
    for (int it = 0; it < 16; it++) {
        const int row = w * 16 + it;
        float4 v = reinterpret_cast<const float4*>(predict)
                       [(size_t)(blk * TM + row) * 32 + lane];
        float ss = v.x * v.x + v.y * v.y + v.z * v.z + v.w * v.w;
        #pragma unroll
        for (int o = 16; o; o >>= 1) ss += __shfl_xor_sync(0xffffffffu, ss, o);
        float r = 1.0f / fmaxf(sqrtf(ss), 1e-12f);
        __half2 h0 = __floats2half2_rn(v.x * r, v.y * r);
        __half2 h1 = __floats2half2_rn(v.z * r, v.w * r);
        unsigned long long pk;
        asm("mov.b64 %0,{%1,%2};" : "=l"(pk)
            : "r"(*(uint32_t*)&h0), "r"(*(uint32_t*)&h1));
        *reinterpret_cast<unsigned long long*>(sA + row * (PADH * 2) + lane * 8) = pk;
    }

    // ---- labels from one-hot (warp per sample) ----
    #pragma unroll 2
    for (int it = 0; it < 16; it++) {
        const int s = w * 16 + it;
        float4 t = reinterpret_cast<const float4*>(target)
                       [(size_t)(blk * TM + s) * 32 + lane];
        int idx = -1;
        if (t.x > 0.5f) idx = lane * 4 + 0;
        if (t.y > 0.5f) idx = lane * 4 + 1;
        if (t.z > 0.5f) idx = lane * 4 + 2;
        if (t.w > 0.5f) idx = lane * 4 + 3;
        #pragma unroll
        for (int o = 16; o; o >>= 1)
            idx = max(idx, __shfl_xor_sync(0xffffffffu, idx, o));
        if (lane == 0) slab[s] = idx;
    }
    __syncthreads();

    // ---- HMMA mainloop: warp w owns rows [w*16, w*16+16), all 128 cols ----
    const int g  = lane >> 2;        // fragment row group 0..7
    const int c  = lane & 3;         // fragment col group 0..3
    const int r0 = w * 16 + g;       // this lane's rows: r0 and r0+8

    // Preload all 8 k-step A fragments (32 u32 regs)
    uint32_t A0[8], A1[8], A2[8], A3[8];
    {
        const char* a_lo = sA + r0 * (PADH * 2) + c * 4;
        const char* a_hi = a_lo + 8 * (PADH * 2);
        #pragma unroll
        for (int ks = 0; ks < 8; ks++) {
            A0[ks] = *(const uint32_t*)(a_lo + ks * 32);
            A2[ks] = *(const uint32_t*)(a_lo + ks * 32 + 16);
            A1[ks] = *(const uint32_t*)(a_hi + ks * 32);
            A3[ks] = *(const uint32_t*)(a_hi + ks * 32 + 16);
        }
    }

    const int lbl0 = slab[r0];
    const int lbl1 = slab[r0 + 8];

    // online logsumexp EXCLUDING the label column; label cosine captured aside
    float m0 = -1e30f, se0 = 0.0f, cs0 = -2.0f;
    float m1 = -1e30f, se1 = 0.0f, cs1 = -2.0f;

    #pragma unroll
    for (int t = 0; t < 16; t++) {
        float c0 = 0.0f, c1 = 0.0f, c2 = 0.0f, c3 = 0.0f;
        const char* bb = sB + (8 * t + g) * (PADH * 2) + c * 4;
        #pragma unroll
        for (int ks = 0; ks < 8; ks++) {
            uint32_t b0 = *(const uint32_t*)(bb + ks * 32);
            uint32_t b1 = *(const uint32_t*)(bb + ks * 32 + 16);
            hmma16816(c0, c1, c2, c3, A0[ks], A1[ks], A2[ks], A3[ks], b0, b1);
        }
        const int n0 = 8 * t + 2 * c;   // this lane's cols in tile t

        // row r0: cols n0, n0+1 (exclude label col, capture cosine)
        {
            float z0 = Sv * c0, z1 = Sv * c1;
            if (n0     == lbl0) { cs0 = c0; z0 = -1e30f; }
            if (n0 + 1 == lbl0) { cs0 = c1; z1 = -1e30f; }
            float nm = fmaxf(m0, fmaxf(z0, z1));
            se0 = se0 * __expf(m0 - nm) + __expf(z0 - nm) + __expf(z1 - nm);
            m0 = nm;
        }
        // row r0+8
        {
            float z0 = Sv * c2, z1 = Sv * c3;
            if (n0     == lbl1) { cs1 = c2; z0 = -1e30f; }
            if (n0 + 1 == lbl1) { cs1 = c3; z1 = -1e30f; }
            float nm = fmaxf(m1, fmaxf(z0, z1));
            se1 = se1 * __expf(m1 - nm) + __expf(z0 - nm) + __expf(z1 - nm);
            m1 = nm;
        }
    }

    // combine across the 4 lanes sharing a row (xor 1, xor 2)
    #pragma unroll
    for (int o = 1; o <= 2; o <<= 1) {
        float om = __shfl_xor_sync(0xffffffffu, m0, o);
        float os = __shfl_xor_sync(0xffffffffu, se0, o);
        float nm = fmaxf(m0, om);
        se0 = se0 * __expf(m0 - nm) + os * __expf(om - nm);
        m0 = nm;
        cs0 = fmaxf(cs0, __shfl_xor_sync(0xffffffffu, cs0, o));

        om = __shfl_xor_sync(0xffffffffu, m1, o);
        os = __shfl_xor_sync(0xffffffffu, se1, o);
        nm = fmaxf(m1, om);
        se1 = se1 * __expf(m1 - nm) + os * __expf(om - nm);
        m1 = nm;
        cs1 = fmaxf(cs1, __shfl_xor_sync(0xffffffffu, cs1, o));
    }

    // per-row NLL (lanes with c==0 contribute; others zero) then warp sum
    float nll = row_nll(m0, se0, cs0) + row_nll(m1, se1, cs1);
    if (c != 0) nll = 0.0f;
    #pragma unroll
    for (int o = 16; o; o >>= 1) nll += __shfl_xor_sync(0xffffffffu, nll, o);
    if (lane == 0) red[w] = nll;
    __syncthreads();

    if (tid == 0) {
        float t = 0.0f;
        #pragma unroll
        for (int i = 0; i < 8; i++) t += red[i];
        g_bsum[blk] = t;
        __threadfence();
        int cdone = atomicAdd(&g_cnt, 1);
        *flag = (cdone == NBLK - 1) ? 1 : 0;
    }
    __syncthreads();

    // last block: deterministic final reduction -> mean
    if (*flag) {
        __threadfence();
        float t = g_bsum[tid] + g_bsum[tid + 256] + g_bsum[tid + 512] + g_bsum[tid + 768];
        red[tid] = t;
        __syncthreads();
        #pragma unroll
        for (int st = 128; st; st >>= 1) {
            if (tid < st) red[tid] += red[tid + st];
            __syncthreads();
        }
        if (tid == 0) {
            out[0] = red[0] / (float)Bn;
            g_cnt  = 0;
        }
    }
}

// ---------------------------------------------------------------------------
extern "C" void kernel_launch(void* const* d_in, const int* in_sizes, int n_in,
                              void* d_out, int out_size)
{
    (void)in_sizes; (void)n_in; (void)out_size;
    const float* predict = (const float*)d_in[0];
    const float* target  = (const float*)d_in[1];
    const float* weight  = (const float*)d_in[2];

    cudaFuncSetAttribute(arc_main, cudaFuncAttributeMaxDynamicSharedMemorySize, SMEM_SZ);

    prep_kernel<<<16, 256>>>(weight);
    arc_main<<<NBLK, 256, SMEM_SZ>>>(predict, target, (float*)d_out);
}

// round 5
// speedup vs baseline: 3.2326x; 1.7835x over previous
#include <cuda_runtime.h>
#include <cuda_fp16.h>
#include <cstdint>

// Problem constants
#define Bn 131072
#define Cn 128
#define En 128
#define TM 128              // samples per block
#define NBLK (Bn / TM)      // 1024 blocks
#define PADH 136            // smem row stride in halves (272B) -> conflict-free frags

// ArcFace constants (m = 1.0, s = 100)
#define COSM 0.5403023058681398f
#define SINM 0.8414709848078965f
#define THv  (-0.5403023058681398f)
#define MMv  0.8414709848078965f
#define Sv   100.0f

// Scratch (no allocation allowed -> device globals)
__device__ __half g_wn16[Cn * En];   // normalized weight fp16, row-major [C][E]
__device__ float  g_bsum[NBLK];
__device__ int    g_cnt;             // zero-init; reset by last block each launch

// smem byte offsets
#define OFF_A    0                   // half[128][136] = 34816 B
#define OFF_B    34816               // half[128][136] = 34816 B
#define OFF_RED  69632               // float[8]
#define OFF_FLAG 69664               // int
#define SMEM_SZ  69696

__device__ __forceinline__ void hmma16816(float& c0, float& c1, float& c2, float& c3,
                                          uint32_t a0, uint32_t a1, uint32_t a2, uint32_t a3,
                                          uint32_t b0, uint32_t b1) {
    asm volatile(
        "mma.sync.aligned.m16n8k16.row.col.f32.f16.f16.f32 "
        "{%0,%1,%2,%3}, {%4,%5,%6,%7}, {%8,%9}, {%0,%1,%2,%3};"
        : "+f"(c0), "+f"(c1), "+f"(c2), "+f"(c3)
        : "r"(a0), "r"(a1), "r"(a2), "r"(a3), "r"(b0), "r"(b1));
}

// ---------------------------------------------------------------------------
// prep: normalize weight rows -> fp16 row-major global. 16 blocks x 256 thr.
// ---------------------------------------------------------------------------
__global__ void prep_kernel(const float* __restrict__ weight)
{
    const int lane = threadIdx.x & 31;
    const int w    = threadIdx.x >> 5;
    const int row  = blockIdx.x * 8 + w;

    float4 v = reinterpret_cast<const float4*>(weight)[row * 32 + lane];
    float ss = v.x * v.x + v.y * v.y + v.z * v.z + v.w * v.w;
    #pragma unroll
    for (int o = 16; o; o >>= 1) ss += __shfl_xor_sync(0xffffffffu, ss, o);
    float r = 1.0f / fmaxf(sqrtf(ss), 1e-12f);

    __half2 h0 = __floats2half2_rn(v.x * r, v.y * r);
    __half2 h1 = __floats2half2_rn(v.z * r, v.w * r);
    unsigned long long pk;
    asm("mov.b64 %0,{%1,%2};" : "=l"(pk)
        : "r"(*(uint32_t*)&h0), "r"(*(uint32_t*)&h1));
    *reinterpret_cast<unsigned long long*>(
        reinterpret_cast<char*>(g_wn16) + row * 256 + lane * 8) = pk;
}

// NLL from label-EXCLUDED (m, se) and label cosine cs. Strictly additive.
__device__ __forceinline__ float row_nll(float m, float se, float cs) {
    float sn  = sqrtf(fmaxf(1.0f - cs * cs, 0.0f));
    float phi = (cs > THv) ? (cs * COSM - sn * SINM) : (cs - MMv);
    float zl  = Sv * phi;
    float mp  = fmaxf(m, zl);
    float se2 = se * __expf(m - mp) + __expf(zl - mp);
    return (mp + __logf(se2)) - zl;
}

// ---------------------------------------------------------------------------
// main kernel
// ---------------------------------------------------------------------------
__global__ void __launch_bounds__(256, 2)
arc_main(const float* __restrict__ predict,
         const float* __restrict__ target,
         float* __restrict__ out)
{
    extern __shared__ char sm[];
    char*  sA   = sm + OFF_A;
    char*  sB   = sm + OFF_B;
    float* red  = (float*)(sm + OFF_RED);
    int*   flag = (int*)(sm + OFF_FLAG);

    const int tid  = threadIdx.x;
    const int lane = tid & 31;
    const int w    = tid >> 5;
    const int blk  = blockIdx.x;
    const int g    = lane >> 2;      // fragment row group 0..7
    const int c    = lane & 3;       // fragment col group 0..3

    // ---- B tile: copy normalized fp16 weights into padded smem (uint4) ----
    {
        const uint4* gw = (const uint4*)g_wn16;   // 2048 uint4
        #pragma unroll
        for (int i = 0; i < 8; i++) {
            int idx = i * 256 + tid;              // uint4 index; 16 per row
            *(uint4*)(sB + (idx >> 4) * (PADH * 2) + (idx & 15) * 16) = gw[idx];
        }
    }

    // ---- A tile: raw fp16 store (no pre-normalization); per-row partials ----
    float ssq[16];    // per-lane partial sum-of-squares for warp-local rows
    float lix[16];    // per-lane partial label index (exact, one-hot dot iota)
    const float i0 = (float)(lane * 4), i1 = i0 + 1.0f, i2 = i0 + 2.0f, i3 = i0 + 3.0f;

    #pragma unroll 4
    for (int it = 0; it < 16; it++) {
        const int row = w * 16 + it;
        const size_t gidx = (size_t)(blk * TM + row) * 32 + lane;
        float4 v = reinterpret_cast<const float4*>(predict)[gidx];
        float4 t = reinterpret_cast<const float4*>(target)[gidx];

        // store raw fp16 immediately (depends only on the load)
        __half2 h0 = __floats2half2_rn(v.x, v.y);
        __half2 h1 = __floats2half2_rn(v.z, v.w);
        unsigned long long pk;
        asm("mov.b64 %0,{%1,%2};" : "=l"(pk)
            : "r"(*(uint32_t*)&h0), "r"(*(uint32_t*)&h1));
        *reinterpret_cast<unsigned long long*>(sA + row * (PADH * 2) + lane * 8) = pk;

        ssq[it] = fmaf(v.x, v.x, fmaf(v.y, v.y, fmaf(v.z, v.z, v.w * v.w)));
        lix[it] = fmaf(t.x, i0, fmaf(t.y, i1, fmaf(t.z, i2, t.w * i3)));
    }

    // ---- one vectorized butterfly: 16 row-sums (norm^2) + 16 labels ----
    #pragma unroll
    for (int o = 16; o; o >>= 1) {
        #pragma unroll
        for (int i = 0; i < 16; i++) {
            ssq[i] += __shfl_xor_sync(0xffffffffu, ssq[i], o);
            lix[i] += __shfl_xor_sync(0xffffffffu, lix[i], o);
        }
    }
    // compile-time selects: this lane's two rows are g and g+8
    float ss0 = 0.f, ss1 = 0.f, lf0 = 0.f, lf1 = 0.f;
    #pragma unroll
    for (int i = 0; i < 8; i++) {
        if (i == g) { ss0 = ssq[i]; lf0 = lix[i]; ss1 = ssq[i + 8]; lf1 = lix[i + 8]; }
    }
    const float invn0 = rsqrtf(fmaxf(ss0, 1e-24f));
    const float invn1 = rsqrtf(fmaxf(ss1, 1e-24f));
    const int   lbl0  = (int)lf0;
    const int   lbl1  = (int)lf1;

    __syncthreads();

    // ---- pass 1: HMMA all 16 tiles, keep 64 dots in registers ----
    const int r0 = w * 16 + g;
    uint32_t A0[8], A1[8], A2[8], A3[8];
    {
        const char* a_lo = sA + r0 * (PADH * 2) + c * 4;
        const char* a_hi = a_lo + 8 * (PADH * 2);
        #pragma unroll
        for (int ks = 0; ks < 8; ks++) {
            A0[ks] = *(const uint32_t*)(a_lo + ks * 32);
            A2[ks] = *(const uint32_t*)(a_lo + ks * 32 + 16);
            A1[ks] = *(const uint32_t*)(a_hi + ks * 32);
            A3[ks] = *(const uint32_t*)(a_hi + ks * 32 + 16);
        }
    }

    float cr0[32], cr1[32];
    #pragma unroll
    for (int t = 0; t < 16; t++) {
        float c0 = 0.f, c1 = 0.f, c2 = 0.f, c3 = 0.f;
        const char* bb = sB + (8 * t + g) * (PADH * 2) + c * 4;
        #pragma unroll
        for (int ks = 0; ks < 8; ks++) {
            uint32_t b0 = *(const uint32_t*)(bb + ks * 32);
            uint32_t b1 = *(const uint32_t*)(bb + ks * 32 + 16);
            hmma16816(c0, c1, c2, c3, A0[ks], A1[ks], A2[ks], A3[ks], b0, b1);
        }
        cr0[2 * t] = c0; cr0[2 * t + 1] = c1;
        cr1[2 * t] = c2; cr1[2 * t + 1] = c3;
    }

    // ---- pass 2: scale, exclude label, 4-way-ILP max, independent exps ----
    const float sI0 = Sv * invn0, sI1 = Sv * invn1;
    const int   q0  = lbl0 - 2 * c;      // match if 8*(j>>1)+(j&1) == q
    const int   q1  = lbl1 - 2 * c;
    float cs0 = -2.0f, cs1 = -2.0f;
    float ma0[4] = {-1e30f, -1e30f, -1e30f, -1e30f};
    float ma1[4] = {-1e30f, -1e30f, -1e30f, -1e30f};

    #pragma unroll
    for (int j = 0; j < 32; j++) {
        const int base = 8 * (j >> 1) + (j & 1);   // compile-time
        float z0 = cr0[j] * sI0;
        if (base == q0) { cs0 = cr0[j] * invn0; z0 = -1e30f; }
        cr0[j] = z0; ma0[j & 3] = fmaxf(ma0[j & 3], z0);
        float z1 = cr1[j] * sI1;
        if (base == q1) { cs1 = cr1[j] * invn1; z1 = -1e30f; }
        cr1[j] = z1; ma1[j & 3] = fmaxf(ma1[j & 3], z1);
    }
    float m0 = fmaxf(fmaxf(ma0[0], ma0[1]), fmaxf(ma0[2], ma0[3]));
    float m1 = fmaxf(fmaxf(ma1[0], ma1[1]), fmaxf(ma1[2], ma1[3]));
    m0 = fmaxf(m0, __shfl_xor_sync(0xffffffffu, m0, 1));
    m0 = fmaxf(m0, __shfl_xor_sync(0xffffffffu, m0, 2));
    m1 = fmaxf(m1, __shfl_xor_sync(0xffffffffu, m1, 1));
    m1 = fmaxf(m1, __shfl_xor_sync(0xffffffffu, m1, 2));

    float s0[4] = {0.f, 0.f, 0.f, 0.f}, s1[4] = {0.f, 0.f, 0.f, 0.f};
    #pragma unroll
    for (int j = 0; j < 32; j++) {
        s0[j & 3] += __expf(cr0[j] - m0);
        s1[j & 3] += __expf(cr1[j] - m1);
    }
    float se0 = (s0[0] + s0[1]) + (s0[2] + s0[3]);
    float se1 = (s1[0] + s1[1]) + (s1[2] + s1[3]);
    se0 += __shfl_xor_sync(0xffffffffu, se0, 1);
    se0 += __shfl_xor_sync(0xffffffffu, se0, 2);
    se1 += __shfl_xor_sync(0xffffffffu, se1, 1);
    se1 += __shfl_xor_sync(0xffffffffu, se1, 2);
    cs0 = fmaxf(cs0, __shfl_xor_sync(0xffffffffu, cs0, 1));
    cs0 = fmaxf(cs0, __shfl_xor_sync(0xffffffffu, cs0, 2));
    cs1 = fmaxf(cs1, __shfl_xor_sync(0xffffffffu, cs1, 1));
    cs1 = fmaxf(cs1, __shfl_xor_sync(0xffffffffu, cs1, 2));

    // per-row NLL (lane c==0 contributes) then warp sum
    float nll = row_nll(m0, se0, cs0) + row_nll(m1, se1, cs1);
    if (c != 0) nll = 0.0f;
    #pragma unroll
    for (int o = 16; o; o >>= 1) nll += __shfl_xor_sync(0xffffffffu, nll, o);
    if (lane == 0) red[w] = nll;
    __syncthreads();

    if (tid == 0) {
        float t = 0.0f;
        #pragma unroll
        for (int i = 0; i < 8; i++) t += red[i];
        g_bsum[blk] = t;
        __threadfence();
        int cdone = atomicAdd(&g_cnt, 1);
        *flag = (cdone == NBLK - 1) ? 1 : 0;
    }
    __syncthreads();

    // last block: deterministic final reduction -> mean
    if (*flag) {
        __threadfence();
        float t = g_bsum[tid] + g_bsum[tid + 256] + g_bsum[tid + 512] + g_bsum[tid + 768];
        float* fr = (float*)(sm + OFF_A);   // reuse smem
        fr[tid] = t;
        __syncthreads();
        #pragma unroll
        for (int st = 128; st; st >>= 1) {
            if (tid < st) fr[tid] += fr[tid + st];
            __syncthreads();
        }
        if (tid == 0) {
            out[0] = fr[0] / (float)Bn;
            g_cnt  = 0;
        }
    }
}

// ---------------------------------------------------------------------------
extern "C" void kernel_launch(void* const* d_in, const int* in_sizes, int n_in,
                              void* d_out, int out_size)
{
    (void)in_sizes; (void)n_in; (void)out_size;
    const float* predict = (const float*)d_in[0];
    const float* target  = (const float*)d_in[1];
    const float* weight  = (const float*)d_in[2];

    cudaFuncSetAttribute(arc_main, cudaFuncAttributeMaxDynamicSharedMemorySize, SMEM_SZ);

    prep_kernel<<<16, 256>>>(weight);
    arc_main<<<NBLK, 256, SMEM_SZ>>>(predict, target, (float*)d_out);
}